// round 1
// baseline (speedup 1.0000x reference)
#include <cuda_runtime.h>
#include <cstdint>

#define N_NODES 100000
#define N_EDGES 800000
#define F 128      // IN_FEATS == N_HIDDEN
#define C 64       // N_CLASSES

#define TM   64    // nodes per block in GEMM kernel
#define PAD  132   // padded row stride for sH (conflict-free column reads)

// Scratch (no cudaMalloc allowed): agg accumulator + degree
__device__ float g_agg[(size_t)N_NODES * F];   // 51.2 MB
__device__ float g_deg[N_NODES];

// ---------------------------------------------------------------------------
// K0: init agg = x (folds the +x[v] self term), deg = 1 (folds the +1)
// ---------------------------------------------------------------------------
__global__ void k_init(const float* __restrict__ x) {
    int i = blockIdx.x * blockDim.x + threadIdx.x;
    const int n4 = N_NODES * F / 4;                 // 3,200,000
    const float4* x4 = (const float4*)x;
    float4* a4 = (float4*)g_agg;
    for (int idx = i; idx < n4; idx += gridDim.x * blockDim.x)
        a4[idx] = x4[idx];
    for (int idx = i; idx < N_NODES; idx += gridDim.x * blockDim.x)
        g_deg[idx] = 1.0f;
}

// ---------------------------------------------------------------------------
// K1: edge scatter. One warp per edge; each lane moves a float4 (32*16B=512B)
// red.global.add.v4.f32: 16B vector reduction, no return -> 4x fewer L2 atomic
// ops than scalar atomicAdd.
// ---------------------------------------------------------------------------
__global__ void __launch_bounds__(256) k_scatter(const float* __restrict__ x,
                                                 const int* __restrict__ src,
                                                 const int* __restrict__ dst) {
    int warp = (blockIdx.x * blockDim.x + threadIdx.x) >> 5;
    int lane = threadIdx.x & 31;
    if (warp >= N_EDGES) return;
    int s = src[warp];
    int d = dst[warp];
    float4 v = ((const float4*)(x + (size_t)s * F))[lane];
    float* p = g_agg + (size_t)d * F + lane * 4;
    asm volatile("red.global.add.v4.f32 [%0], {%1,%2,%3,%4};"
                 :: "l"(p), "f"(v.x), "f"(v.y), "f"(v.z), "f"(v.w)
                 : "memory");
    if (lane == 0) atomicAdd(&g_deg[d], 1.0f);
}

// ---------------------------------------------------------------------------
// K2: fused  hn = agg/deg ; emb = relu(hn@W1 + b1) ; out = emb@W2 + b2
// Block: 256 threads, TM=64 nodes. W1 (64KB) + W2 (32KB) + hn/emb tile (33KB)
// live in dynamic shared memory. Register tiles: GEMM1 4x8, GEMM2 4x4.
// ---------------------------------------------------------------------------
#define K2_SMEM ((F*F + F*C + TM*PAD) * (int)sizeof(float))   // 132,096 B

__global__ void __launch_bounds__(256) k_gemm(
    const float* __restrict__ W1, const float* __restrict__ b1,
    const float* __restrict__ W2, const float* __restrict__ b2,
    float* __restrict__ out, float* __restrict__ emb)
{
    extern __shared__ float smem[];
    float* sW1 = smem;            // [k][col] 128x128
    float* sW2 = sW1 + F * F;     // [k][col] 128x64
    float* sH  = sW2 + F * C;     // [row][k] 64x132 (hn, then reused for emb)

    const int tid   = threadIdx.x;
    const int node0 = blockIdx.x * TM;

    // --- load weights to shared ---
    {
        const float4* w14 = (const float4*)W1;
        float4* s14 = (float4*)sW1;
        #pragma unroll
        for (int i = tid; i < F * F / 4; i += 256) s14[i] = w14[i];
        const float4* w24 = (const float4*)W2;
        float4* s24 = (float4*)sW2;
        #pragma unroll
        for (int i = tid; i < F * C / 4; i += 256) s24[i] = w24[i];
    }

    // --- load hn tile: hn = agg / deg  (deg already includes the +1) ---
    {
        int r0 = tid >> 5;          // 0..7
        int c4 = tid & 31;          // float4 column 0..31
        #pragma unroll
        for (int rr = r0; rr < TM; rr += 8) {
            int node = node0 + rr;
            float4 v = make_float4(0.f, 0.f, 0.f, 0.f);
            if (node < N_NODES) {
                v = ((const float4*)(g_agg + (size_t)node * F))[c4];
                float inv = 1.0f / g_deg[node];
                v.x *= inv; v.y *= inv; v.z *= inv; v.w *= inv;
            }
            *(float4*)(sH + rr * PAD + c4 * 4) = v;
        }
    }
    __syncthreads();

    const int tx = tid & 15;        // col group
    const int ty = tid >> 4;        // node group 0..15
    const int colb = tx * 8;        // GEMM1 columns [colb, colb+8)
    const int row0 = ty * 4;        // rows [row0, row0+4)

    // --- GEMM1: [64x128] = sH[64x128] @ sW1[128x128] ---
    float acc[4][8];
    #pragma unroll
    for (int i = 0; i < 4; i++)
        #pragma unroll
        for (int j = 0; j < 8; j++) acc[i][j] = 0.f;

    #pragma unroll 4
    for (int k = 0; k < F; k++) {
        float a0 = sH[(row0 + 0) * PAD + k];
        float a1 = sH[(row0 + 1) * PAD + k];
        float a2 = sH[(row0 + 2) * PAD + k];
        float a3 = sH[(row0 + 3) * PAD + k];
        float4 bA = *(const float4*)(sW1 + k * F + colb);
        float4 bB = *(const float4*)(sW1 + k * F + colb + 4);
        float b[8] = {bA.x, bA.y, bA.z, bA.w, bB.x, bB.y, bB.z, bB.w};
        #pragma unroll
        for (int j = 0; j < 8; j++) {
            acc[0][j] += a0 * b[j];
            acc[1][j] += a1 * b[j];
            acc[2][j] += a2 * b[j];
            acc[3][j] += a3 * b[j];
        }
    }
    __syncthreads();   // all reads of sH (hn) done before overwrite

    // --- epilogue1: +b1, relu, write emb (global) and sH (for GEMM2) ---
    {
        float4 biasA = *(const float4*)(b1 + colb);
        float4 biasB = *(const float4*)(b1 + colb + 4);
        #pragma unroll
        for (int i = 0; i < 4; i++) {
            int node = node0 + row0 + i;
            float4 vA, vB;
            vA.x = fmaxf(acc[i][0] + biasA.x, 0.f);
            vA.y = fmaxf(acc[i][1] + biasA.y, 0.f);
            vA.z = fmaxf(acc[i][2] + biasA.z, 0.f);
            vA.w = fmaxf(acc[i][3] + biasA.w, 0.f);
            vB.x = fmaxf(acc[i][4] + biasB.x, 0.f);
            vB.y = fmaxf(acc[i][5] + biasB.y, 0.f);
            vB.z = fmaxf(acc[i][6] + biasB.z, 0.f);
            vB.w = fmaxf(acc[i][7] + biasB.w, 0.f);
            *(float4*)(sH + (row0 + i) * PAD + colb)     = vA;
            *(float4*)(sH + (row0 + i) * PAD + colb + 4) = vB;
            if (node < N_NODES) {
                *(float4*)(emb + (size_t)node * F + colb)     = vA;
                *(float4*)(emb + (size_t)node * F + colb + 4) = vB;
            }
        }
    }
    __syncthreads();

    // --- GEMM2: [64x64] = sH(emb)[64x128] @ sW2[128x64] ---
    const int colc = tx * 4;        // GEMM2 columns [colc, colc+4)
    float acc2[4][4];
    #pragma unroll
    for (int i = 0; i < 4; i++)
        #pragma unroll
        for (int j = 0; j < 4; j++) acc2[i][j] = 0.f;

    #pragma unroll 4
    for (int k = 0; k < F; k++) {
        float a0 = sH[(row0 + 0) * PAD + k];
        float a1 = sH[(row0 + 1) * PAD + k];
        float a2 = sH[(row0 + 2) * PAD + k];
        float a3 = sH[(row0 + 3) * PAD + k];
        float4 b4 = *(const float4*)(sW2 + k * C + colc);
        float b[4] = {b4.x, b4.y, b4.z, b4.w};
        #pragma unroll
        for (int j = 0; j < 4; j++) {
            acc2[0][j] += a0 * b[j];
            acc2[1][j] += a1 * b[j];
            acc2[2][j] += a2 * b[j];
            acc2[3][j] += a3 * b[j];
        }
    }

    // --- epilogue2: +b2, write out ---
    {
        float4 bias = *(const float4*)(b2 + colc);
        #pragma unroll
        for (int i = 0; i < 4; i++) {
            int node = node0 + row0 + i;
            if (node < N_NODES) {
                float4 v;
                v.x = acc2[i][0] + bias.x;
                v.y = acc2[i][1] + bias.y;
                v.z = acc2[i][2] + bias.z;
                v.w = acc2[i][3] + bias.w;
                *(float4*)(out + (size_t)node * C + colc) = v;
            }
        }
    }
}

// ---------------------------------------------------------------------------
extern "C" void kernel_launch(void* const* d_in, const int* in_sizes, int n_in,
                              void* d_out, int out_size) {
    const float* x   = (const float*)d_in[0];
    const int*   src = (const int*)d_in[1];
    const int*   dst = (const int*)d_in[2];
    const float* W1  = (const float*)d_in[3];
    const float* b1  = (const float*)d_in[4];
    const float* W2  = (const float*)d_in[5];
    const float* b2  = (const float*)d_in[6];

    float* out = (float*)d_out;                       // [N_NODES, 64]
    float* emb = out + (size_t)N_NODES * C;           // [N_NODES, 128]

    // K0: agg = x, deg = 1
    k_init<<<12500, 256>>>(x);

    // K1: warp-per-edge scatter (vector reductions)
    int warps = N_EDGES;
    int blocks = (warps * 32 + 255) / 256;            // 100000
    k_scatter<<<blocks, 256>>>(x, src, dst);

    // K2: fused normalize + GEMM1 + relu + GEMM2
    cudaFuncSetAttribute(k_gemm, cudaFuncAttributeMaxDynamicSharedMemorySize,
                         K2_SMEM);
    int gblocks = (N_NODES + TM - 1) / TM;            // 1563
    k_gemm<<<gblocks, 256, K2_SMEM>>>(W1, b1, W2, b2, out, emb);
}

// round 2
// speedup vs baseline: 1.3023x; 1.3023x over previous
#include <cuda_runtime.h>
#include <cstdint>

#define N_NODES 100000
#define N_EDGES 800000
#define F 128      // IN_FEATS == N_HIDDEN
#define C 64       // N_CLASSES

#define TM   64    // nodes per block in GEMM kernel
#define PAD  132   // padded row stride for sH (conflict-free column reads)

#define SCAN_B 512
#define N_SCANBLK ((N_NODES + SCAN_B - 1) / SCAN_B)   // 196

// Scratch (no cudaMalloc allowed)
__device__ float g_hn[(size_t)N_NODES * F];    // normalized h_neigh, 51.2 MB
__device__ int   g_esrc[N_EDGES];              // edge srcs sorted by dst
__device__ int   g_deg[N_NODES];
__device__ int   g_part[N_NODES];              // intra-block exclusive prefix
__device__ int   g_rowptr[N_NODES];
__device__ int   g_cursor[N_NODES];
__device__ int   g_bsum[N_SCANBLK];
__device__ int   g_boff[N_SCANBLK];

// ---------------------------------------------------------------------------
// K0: zero degree histogram
// ---------------------------------------------------------------------------
__global__ void k_zero() {
    int i = blockIdx.x * blockDim.x + threadIdx.x;
    if (i < N_NODES) g_deg[i] = 0;
}

// ---------------------------------------------------------------------------
// K1: degree histogram
// ---------------------------------------------------------------------------
__global__ void k_hist(const int* __restrict__ dst) {
    int i = blockIdx.x * blockDim.x + threadIdx.x;
    if (i < N_EDGES) atomicAdd(&g_deg[dst[i]], 1);
}

// ---------------------------------------------------------------------------
// K2a: per-block exclusive scan of degrees (Hillis-Steele in smem)
// ---------------------------------------------------------------------------
__global__ void __launch_bounds__(SCAN_B) k_scan_block() {
    __shared__ int s[SCAN_B];
    int tid = threadIdx.x;
    int v = blockIdx.x * SCAN_B + tid;
    int d = (v < N_NODES) ? g_deg[v] : 0;
    s[tid] = d;
    __syncthreads();
    #pragma unroll
    for (int off = 1; off < SCAN_B; off <<= 1) {
        int t = (tid >= off) ? s[tid - off] : 0;
        __syncthreads();
        s[tid] += t;
        __syncthreads();
    }
    if (v < N_NODES) g_part[v] = s[tid] - d;       // exclusive
    if (tid == SCAN_B - 1) g_bsum[blockIdx.x] = s[tid];
}

// ---------------------------------------------------------------------------
// K2b: single-block exclusive scan of 196 block sums
// ---------------------------------------------------------------------------
__global__ void __launch_bounds__(256) k_scan_top() {
    __shared__ int s[256];
    int tid = threadIdx.x;
    int d = (tid < N_SCANBLK) ? g_bsum[tid] : 0;
    s[tid] = d;
    __syncthreads();
    #pragma unroll
    for (int off = 1; off < 256; off <<= 1) {
        int t = (tid >= off) ? s[tid - off] : 0;
        __syncthreads();
        s[tid] += t;
        __syncthreads();
    }
    if (tid < N_SCANBLK) g_boff[tid] = s[tid] - d; // exclusive
}

// ---------------------------------------------------------------------------
// K2c: rowptr = intra + block offset; cursor = rowptr
// ---------------------------------------------------------------------------
__global__ void k_rowptr() {
    int v = blockIdx.x * blockDim.x + threadIdx.x;
    if (v < N_NODES) {
        int r = g_part[v] + g_boff[v >> 9];        // 2^9 = SCAN_B
        g_rowptr[v] = r;
        g_cursor[v] = r;
    }
}

// ---------------------------------------------------------------------------
// K3: scatter edges into dst-sorted order
// ---------------------------------------------------------------------------
__global__ void k_fill(const int* __restrict__ src, const int* __restrict__ dst) {
    int e = blockIdx.x * blockDim.x + threadIdx.x;
    if (e < N_EDGES) {
        int pos = atomicAdd(&g_cursor[dst[e]], 1);
        g_esrc[pos] = src[e];
    }
}

// ---------------------------------------------------------------------------
// K4: gather-sum per node. One warp per node, lane owns one float4 (4 feats).
// hn[v] = (x[v] + sum_{u->v} x[u]) / (deg(v)+1)
// ---------------------------------------------------------------------------
__global__ void __launch_bounds__(256) k_gather(const float* __restrict__ x) {
    int warp = (blockIdx.x * blockDim.x + threadIdx.x) >> 5;
    int lane = threadIdx.x & 31;
    if (warp >= N_NODES) return;
    const int v = warp;
    const float4* x4 = (const float4*)x;

    float4 acc = x4[(size_t)v * 32 + lane];        // self term
    int start = g_rowptr[v];
    int deg   = g_deg[v];
    int end   = start + deg;

    int j = start;
    // unroll by 2 for memory-level parallelism
    for (; j + 1 < end; j += 2) {
        int s0 = __ldg(&g_esrc[j]);
        int s1 = __ldg(&g_esrc[j + 1]);
        float4 a = x4[(size_t)s0 * 32 + lane];
        float4 b = x4[(size_t)s1 * 32 + lane];
        acc.x += a.x + b.x; acc.y += a.y + b.y;
        acc.z += a.z + b.z; acc.w += a.w + b.w;
    }
    if (j < end) {
        int s0 = __ldg(&g_esrc[j]);
        float4 a = x4[(size_t)s0 * 32 + lane];
        acc.x += a.x; acc.y += a.y; acc.z += a.z; acc.w += a.w;
    }

    float inv = 1.0f / (float)(deg + 1);
    acc.x *= inv; acc.y *= inv; acc.z *= inv; acc.w *= inv;
    ((float4*)g_hn)[(size_t)v * 32 + lane] = acc;
}

// ---------------------------------------------------------------------------
// K5: fused  emb = relu(hn@W1 + b1) ; out = emb@W2 + b2
// ---------------------------------------------------------------------------
#define K5_SMEM ((F*F + F*C + TM*PAD) * (int)sizeof(float))   // 132,096 B

__global__ void __launch_bounds__(256) k_gemm(
    const float* __restrict__ W1, const float* __restrict__ b1,
    const float* __restrict__ W2, const float* __restrict__ b2,
    float* __restrict__ out, float* __restrict__ emb)
{
    extern __shared__ float smem[];
    float* sW1 = smem;            // [k][col] 128x128
    float* sW2 = sW1 + F * F;     // [k][col] 128x64
    float* sH  = sW2 + F * C;     // [row][k] 64x132 (hn, then reused for emb)

    const int tid   = threadIdx.x;
    const int node0 = blockIdx.x * TM;

    // --- load weights to shared ---
    {
        const float4* w14 = (const float4*)W1;
        float4* s14 = (float4*)sW1;
        #pragma unroll
        for (int i = tid; i < F * F / 4; i += 256) s14[i] = w14[i];
        const float4* w24 = (const float4*)W2;
        float4* s24 = (float4*)sW2;
        #pragma unroll
        for (int i = tid; i < F * C / 4; i += 256) s24[i] = w24[i];
    }

    // --- load hn tile (already normalized) ---
    {
        int r0 = tid >> 5;          // 0..7
        int c4 = tid & 31;          // float4 column 0..31
        #pragma unroll
        for (int rr = r0; rr < TM; rr += 8) {
            int node = node0 + rr;
            float4 v = make_float4(0.f, 0.f, 0.f, 0.f);
            if (node < N_NODES)
                v = ((const float4*)g_hn)[(size_t)node * 32 + c4];
            *(float4*)(sH + rr * PAD + c4 * 4) = v;
        }
    }
    __syncthreads();

    const int tx = tid & 15;        // col group
    const int ty = tid >> 4;        // node group 0..15
    const int colb = tx * 8;        // GEMM1 columns [colb, colb+8)
    const int row0 = ty * 4;        // rows [row0, row0+4)

    // --- GEMM1: [64x128] = sH[64x128] @ sW1[128x128] ---
    float acc[4][8];
    #pragma unroll
    for (int i = 0; i < 4; i++)
        #pragma unroll
        for (int j = 0; j < 8; j++) acc[i][j] = 0.f;

    #pragma unroll 4
    for (int k = 0; k < F; k++) {
        float a0 = sH[(row0 + 0) * PAD + k];
        float a1 = sH[(row0 + 1) * PAD + k];
        float a2 = sH[(row0 + 2) * PAD + k];
        float a3 = sH[(row0 + 3) * PAD + k];
        float4 bA = *(const float4*)(sW1 + k * F + colb);
        float4 bB = *(const float4*)(sW1 + k * F + colb + 4);
        float b[8] = {bA.x, bA.y, bA.z, bA.w, bB.x, bB.y, bB.z, bB.w};
        #pragma unroll
        for (int j = 0; j < 8; j++) {
            acc[0][j] += a0 * b[j];
            acc[1][j] += a1 * b[j];
            acc[2][j] += a2 * b[j];
            acc[3][j] += a3 * b[j];
        }
    }
    __syncthreads();   // all reads of sH (hn) done before overwrite

    // --- epilogue1: +b1, relu, write emb (global) and sH (for GEMM2) ---
    {
        float4 biasA = *(const float4*)(b1 + colb);
        float4 biasB = *(const float4*)(b1 + colb + 4);
        #pragma unroll
        for (int i = 0; i < 4; i++) {
            int node = node0 + row0 + i;
            float4 vA, vB;
            vA.x = fmaxf(acc[i][0] + biasA.x, 0.f);
            vA.y = fmaxf(acc[i][1] + biasA.y, 0.f);
            vA.z = fmaxf(acc[i][2] + biasA.z, 0.f);
            vA.w = fmaxf(acc[i][3] + biasA.w, 0.f);
            vB.x = fmaxf(acc[i][4] + biasB.x, 0.f);
            vB.y = fmaxf(acc[i][5] + biasB.y, 0.f);
            vB.z = fmaxf(acc[i][6] + biasB.z, 0.f);
            vB.w = fmaxf(acc[i][7] + biasB.w, 0.f);
            *(float4*)(sH + (row0 + i) * PAD + colb)     = vA;
            *(float4*)(sH + (row0 + i) * PAD + colb + 4) = vB;
            if (node < N_NODES) {
                *(float4*)(emb + (size_t)node * F + colb)     = vA;
                *(float4*)(emb + (size_t)node * F + colb + 4) = vB;
            }
        }
    }
    __syncthreads();

    // --- GEMM2: [64x64] = sH(emb)[64x128] @ sW2[128x64] ---
    const int colc = tx * 4;        // GEMM2 columns [colc, colc+4)
    float acc2[4][4];
    #pragma unroll
    for (int i = 0; i < 4; i++)
        #pragma unroll
        for (int j = 0; j < 4; j++) acc2[i][j] = 0.f;

    #pragma unroll 4
    for (int k = 0; k < F; k++) {
        float a0 = sH[(row0 + 0) * PAD + k];
        float a1 = sH[(row0 + 1) * PAD + k];
        float a2 = sH[(row0 + 2) * PAD + k];
        float a3 = sH[(row0 + 3) * PAD + k];
        float4 b4 = *(const float4*)(sW2 + k * C + colc);
        float b[4] = {b4.x, b4.y, b4.z, b4.w};
        #pragma unroll
        for (int j = 0; j < 4; j++) {
            acc2[0][j] += a0 * b[j];
            acc2[1][j] += a1 * b[j];
            acc2[2][j] += a2 * b[j];
            acc2[3][j] += a3 * b[j];
        }
    }

    // --- epilogue2: +b2, write out ---
    {
        float4 bias = *(const float4*)(b2 + colc);
        #pragma unroll
        for (int i = 0; i < 4; i++) {
            int node = node0 + row0 + i;
            if (node < N_NODES) {
                float4 v;
                v.x = acc2[i][0] + bias.x;
                v.y = acc2[i][1] + bias.y;
                v.z = acc2[i][2] + bias.z;
                v.w = acc2[i][3] + bias.w;
                *(float4*)(out + (size_t)node * C + colc) = v;
            }
        }
    }
}

// ---------------------------------------------------------------------------
extern "C" void kernel_launch(void* const* d_in, const int* in_sizes, int n_in,
                              void* d_out, int out_size) {
    const float* x   = (const float*)d_in[0];
    const int*   src = (const int*)d_in[1];
    const int*   dst = (const int*)d_in[2];
    const float* W1  = (const float*)d_in[3];
    const float* b1  = (const float*)d_in[4];
    const float* W2  = (const float*)d_in[5];
    const float* b2  = (const float*)d_in[6];

    float* out = (float*)d_out;                       // [N_NODES, 64]
    float* emb = out + (size_t)N_NODES * C;           // [N_NODES, 128]

    // CSR build
    k_zero<<<(N_NODES + 255) / 256, 256>>>();
    k_hist<<<(N_EDGES + 255) / 256, 256>>>(dst);
    k_scan_block<<<N_SCANBLK, SCAN_B>>>();
    k_scan_top<<<1, 256>>>();
    k_rowptr<<<(N_NODES + 255) / 256, 256>>>();
    k_fill<<<(N_EDGES + 255) / 256, 256>>>(src, dst);

    // gather-sum + normalize
    k_gather<<<(N_NODES * 32 + 255) / 256, 256>>>(x);

    // fused GEMM1 + relu + GEMM2
    cudaFuncSetAttribute(k_gemm, cudaFuncAttributeMaxDynamicSharedMemorySize,
                         K5_SMEM);
    int gblocks = (N_NODES + TM - 1) / TM;            // 1563
    k_gemm<<<gblocks, 256, K5_SMEM>>>(W1, b1, W2, b2, out, emb);
}

// round 4
// speedup vs baseline: 2.3885x; 1.8341x over previous
#include <cuda_runtime.h>
#include <cuda_bf16.h>
#include <cstdint>

#define N_NODES 100000
#define N_EDGES 800000
#define F 128      // IN_FEATS == N_HIDDEN
#define C 64       // N_CLASSES

#define SCAN_B 512
#define N_SCANBLK ((N_NODES + SCAN_B - 1) / SCAN_B)   // 196

// ---------------------------------------------------------------------------
// Scratch (no cudaMalloc allowed)
// ---------------------------------------------------------------------------
__device__ __nv_bfloat16 g_hnh[(size_t)N_NODES * F];   // hn hi, 25.6 MB
__device__ __nv_bfloat16 g_hnl[(size_t)N_NODES * F];   // hn lo, 25.6 MB
__device__ __nv_bfloat16 g_w1h[F * F], g_w1l[F * F];   // W1^T as [N][K]
__device__ __nv_bfloat16 g_w2h[C * F], g_w2l[C * F];   // W2^T as [N][K]
__device__ int g_esrc[N_EDGES];
__device__ int g_deg[N_NODES];
__device__ int g_part[N_NODES];
__device__ int g_rowptr[N_NODES];
__device__ int g_cursor[N_NODES];
__device__ int g_bsum[N_SCANBLK];
__device__ int g_boff[N_SCANBLK];

// ---------------------------------------------------------------------------
// mma.sync / ldmatrix helpers (portable PTX, works on compute_103 virtual arch)
// ---------------------------------------------------------------------------
__device__ __forceinline__ uint32_t smem_u32(const void* p) {
    uint32_t a;
    asm("{ .reg .u64 t; cvta.to.shared.u64 t, %1; cvt.u32.u64 %0, t; }"
        : "=r"(a) : "l"(p));
    return a;
}
#define LDSM4(r0, r1, r2, r3, addr) \
    asm volatile("ldmatrix.sync.aligned.m8n8.x4.shared.b16 {%0,%1,%2,%3}, [%4];" \
                 : "=r"(r0), "=r"(r1), "=r"(r2), "=r"(r3) : "r"(addr))
#define MMA16816(c, a, b) \
    asm volatile("mma.sync.aligned.m16n8k16.row.col.f32.bf16.bf16.f32 " \
                 "{%0,%1,%2,%3}, {%4,%5,%6,%7}, {%8,%9}, {%0,%1,%2,%3};" \
                 : "+f"((c)[0]), "+f"((c)[1]), "+f"((c)[2]), "+f"((c)[3]) \
                 : "r"((a)[0]), "r"((a)[1]), "r"((a)[2]), "r"((a)[3]), \
                   "r"((b)[0]), "r"((b)[1]))

// ---------------------------------------------------------------------------
// CSR build kernels
// ---------------------------------------------------------------------------
__global__ void k_zero() {
    int i = blockIdx.x * blockDim.x + threadIdx.x;
    if (i < N_NODES) g_deg[i] = 0;
}
__global__ void k_hist(const int* __restrict__ dst) {
    int i = blockIdx.x * blockDim.x + threadIdx.x;
    if (i < N_EDGES) atomicAdd(&g_deg[dst[i]], 1);
}
__global__ void __launch_bounds__(SCAN_B) k_scan_block() {
    __shared__ int s[SCAN_B];
    int tid = threadIdx.x;
    int v = blockIdx.x * SCAN_B + tid;
    int d = (v < N_NODES) ? g_deg[v] : 0;
    s[tid] = d;
    __syncthreads();
    #pragma unroll
    for (int off = 1; off < SCAN_B; off <<= 1) {
        int t = (tid >= off) ? s[tid - off] : 0;
        __syncthreads();
        s[tid] += t;
        __syncthreads();
    }
    if (v < N_NODES) g_part[v] = s[tid] - d;
    if (tid == SCAN_B - 1) g_bsum[blockIdx.x] = s[tid];
}
__global__ void __launch_bounds__(256) k_scan_top() {
    __shared__ int s[256];
    int tid = threadIdx.x;
    int d = (tid < N_SCANBLK) ? g_bsum[tid] : 0;
    s[tid] = d;
    __syncthreads();
    #pragma unroll
    for (int off = 1; off < 256; off <<= 1) {
        int t = (tid >= off) ? s[tid - off] : 0;
        __syncthreads();
        s[tid] += t;
        __syncthreads();
    }
    if (tid < N_SCANBLK) g_boff[tid] = s[tid] - d;
}
__global__ void k_rowptr() {
    int v = blockIdx.x * blockDim.x + threadIdx.x;
    if (v < N_NODES) {
        int r = g_part[v] + g_boff[v >> 9];
        g_rowptr[v] = r;
        g_cursor[v] = r;
    }
}
__global__ void k_fill(const int* __restrict__ src, const int* __restrict__ dst) {
    int e = blockIdx.x * blockDim.x + threadIdx.x;
    if (e < N_EDGES) {
        int pos = atomicAdd(&g_cursor[dst[e]], 1);
        g_esrc[pos] = src[e];
    }
}

// ---------------------------------------------------------------------------
// Weight prep: transpose to [N][K] and split fp32 -> bf16 hi + lo
// ---------------------------------------------------------------------------
__global__ void k_wprep(const float* __restrict__ W1, const float* __restrict__ W2) {
    int i = blockIdx.x * blockDim.x + threadIdx.x;
    if (i < F * F) {
        int k = i / F, n = i % F;
        float v = W1[i];                       // W1[k][n]
        __nv_bfloat16 h = __float2bfloat16(v);
        g_w1h[n * F + k] = h;
        g_w1l[n * F + k] = __float2bfloat16(v - __bfloat162float(h));
    }
    if (i < C * F) {
        int k = i / C, n = i % C;
        float v = W2[i];                       // W2[k][n]
        __nv_bfloat16 h = __float2bfloat16(v);
        g_w2h[n * F + k] = h;
        g_w2l[n * F + k] = __float2bfloat16(v - __bfloat162float(h));
    }
}

// ---------------------------------------------------------------------------
// Gather-sum per node, emit bf16 hi/lo. One warp per node, lane owns float4.
// ---------------------------------------------------------------------------
__global__ void __launch_bounds__(256) k_gather(const float* __restrict__ x) {
    int warp = (blockIdx.x * blockDim.x + threadIdx.x) >> 5;
    int lane = threadIdx.x & 31;
    if (warp >= N_NODES) return;
    const int v = warp;
    const float4* x4 = (const float4*)x;

    float4 acc = x4[(size_t)v * 32 + lane];        // self term
    int start = g_rowptr[v];
    int deg   = g_deg[v];
    int end   = start + deg;

    int j = start;
    for (; j + 1 < end; j += 2) {
        int s0 = __ldg(&g_esrc[j]);
        int s1 = __ldg(&g_esrc[j + 1]);
        float4 a = x4[(size_t)s0 * 32 + lane];
        float4 b = x4[(size_t)s1 * 32 + lane];
        acc.x += a.x + b.x; acc.y += a.y + b.y;
        acc.z += a.z + b.z; acc.w += a.w + b.w;
    }
    if (j < end) {
        int s0 = __ldg(&g_esrc[j]);
        float4 a = x4[(size_t)s0 * 32 + lane];
        acc.x += a.x; acc.y += a.y; acc.z += a.z; acc.w += a.w;
    }

    float inv = 1.0f / (float)(deg + 1);
    acc.x *= inv; acc.y *= inv; acc.z *= inv; acc.w *= inv;

    __nv_bfloat16 h0 = __float2bfloat16(acc.x);
    __nv_bfloat16 h1 = __float2bfloat16(acc.y);
    __nv_bfloat16 h2 = __float2bfloat16(acc.z);
    __nv_bfloat16 h3 = __float2bfloat16(acc.w);
    __nv_bfloat16 l0 = __float2bfloat16(acc.x - __bfloat162float(h0));
    __nv_bfloat16 l1 = __float2bfloat16(acc.y - __bfloat162float(h1));
    __nv_bfloat16 l2 = __float2bfloat16(acc.z - __bfloat162float(h2));
    __nv_bfloat16 l3 = __float2bfloat16(acc.w - __bfloat162float(h3));

    __nv_bfloat162 ph0 = __halves2bfloat162(h0, h1);
    __nv_bfloat162 ph1 = __halves2bfloat162(h2, h3);
    __nv_bfloat162 pl0 = __halves2bfloat162(l0, l1);
    __nv_bfloat162 pl1 = __halves2bfloat162(l2, l3);
    uint2 hv, lv;
    hv.x = *(uint32_t*)&ph0; hv.y = *(uint32_t*)&ph1;
    lv.x = *(uint32_t*)&pl0; lv.y = *(uint32_t*)&pl1;
    ((uint2*)g_hnh)[(size_t)v * 32 + lane] = hv;
    ((uint2*)g_hnl)[(size_t)v * 32 + lane] = lv;
}

// ---------------------------------------------------------------------------
// mma.sync fused GEMM: emb = relu(hn@W1+b1); out = emb@W2+b2
// CTA: 128 nodes, 256 threads (8 warps). bf16 hi/lo 3-chain split, fp32 accum.
// smem tiles at 272B row stride (136 bf16) -> conflict-free ldmatrix.
// ---------------------------------------------------------------------------
#define RS 136                              // row stride in bf16
#define RSB (RS * 2)                        // row stride in bytes (272)
#define SM_BIAS  0                          // 192 floats
#define SM_AH    1024
#define SM_AL    (SM_AH  + 128 * RSB)       // +34816
#define SM_W1H   (SM_AL  + 128 * RSB)
#define SM_W1L   (SM_W1H + 128 * RSB)
#define SM_W2H   (SM_W1L + 128 * RSB)
#define SM_W2L   (SM_W2H + 64 * RSB)
#define SMEM_MM  (SM_W2L + 64 * RSB)        // 175,872 B

__global__ void __launch_bounds__(256) k_gemm_mma(
    const float* __restrict__ b1, const float* __restrict__ b2,
    float* __restrict__ out, float* __restrict__ emb)
{
    extern __shared__ char smem[];
    const uint32_t sb = smem_u32(smem);
    const int tid  = threadIdx.x;
    const int wid  = tid >> 5;
    const int lane = tid & 31;
    const int node0 = blockIdx.x * 128;

    float* sBias = (float*)(smem + SM_BIAS);

    // --- stage bias ---
    if (tid < F) sBias[tid] = b1[tid];
    else if (tid < F + C) sBias[tid] = b2[tid - F];

    // --- stage weights (row-major, stride RS) ---
    {
        const uint4* w1h4 = (const uint4*)g_w1h;
        const uint4* w1l4 = (const uint4*)g_w1l;
        #pragma unroll
        for (int i = tid; i < 128 * 16; i += 256) {
            int r = i >> 4, c = i & 15;
            *(uint4*)(smem + SM_W1H + r * RSB + c * 16) = w1h4[i];
            *(uint4*)(smem + SM_W1L + r * RSB + c * 16) = w1l4[i];
        }
        const uint4* w2h4 = (const uint4*)g_w2h;
        const uint4* w2l4 = (const uint4*)g_w2l;
        #pragma unroll
        for (int i = tid; i < 64 * 16; i += 256) {
            int r = i >> 4, c = i & 15;
            *(uint4*)(smem + SM_W2H + r * RSB + c * 16) = w2h4[i];
            *(uint4*)(smem + SM_W2L + r * RSB + c * 16) = w2l4[i];
        }
    }
    // --- stage A (hn hi/lo) ---
    {
        #pragma unroll
        for (int i = tid; i < 128 * 16; i += 256) {
            int r = i >> 4, c = i & 15;
            int node = node0 + r;
            uint4 vh = make_uint4(0, 0, 0, 0), vl = make_uint4(0, 0, 0, 0);
            if (node < N_NODES) {
                vh = ((const uint4*)g_hnh)[(size_t)node * 16 + c];
                vl = ((const uint4*)g_hnl)[(size_t)node * 16 + c];
            }
            *(uint4*)(smem + SM_AH + r * RSB + c * 16) = vh;
            *(uint4*)(smem + SM_AL + r * RSB + c * 16) = vl;
        }
    }
    __syncthreads();

    // ldmatrix per-lane address components
    const int g  = lane >> 3, lr = lane & 7;
    const int a_row = lr + ((g & 1) << 3);        // 0..15 within m16 tile
    const int a_kof = (g >> 1) << 3;              // 0 or 8
    const int b_row = lr + ((g >> 1) << 3);       // 0..15 within n16 pair
    const int b_kof = (g & 1) << 3;               // 0 or 8

    const int wm = wid & 3;                       // M quarter: rows [wm*32, +32)
    const int wn = wid >> 2;                      // N half:    cols [wn*64, +64)

    // ================= GEMM1: [128 x 128] ==================
    float acc[2][8][4];
    #pragma unroll
    for (int m = 0; m < 2; m++)
        #pragma unroll
        for (int n = 0; n < 8; n++)
            #pragma unroll
            for (int q = 0; q < 4; q++) acc[m][n][q] = 0.f;

    #pragma unroll
    for (int ks = 0; ks < 8; ks++) {
        const int k0 = ks * 16;
        uint32_t ah[2][4], al[2][4];
        #pragma unroll
        for (int m = 0; m < 2; m++) {
            int row = wm * 32 + m * 16 + a_row;
            uint32_t off = row * RSB + (k0 + a_kof) * 2;
            LDSM4(ah[m][0], ah[m][1], ah[m][2], ah[m][3], sb + SM_AH + off);
            LDSM4(al[m][0], al[m][1], al[m][2], al[m][3], sb + SM_AL + off);
        }
        uint32_t bh[8][2], bl[8][2];
        #pragma unroll
        for (int nn = 0; nn < 4; nn++) {
            int row = wn * 64 + nn * 16 + b_row;
            uint32_t off = row * RSB + (k0 + b_kof) * 2;
            LDSM4(bh[2*nn][0], bh[2*nn][1], bh[2*nn+1][0], bh[2*nn+1][1],
                  sb + SM_W1H + off);
            LDSM4(bl[2*nn][0], bl[2*nn][1], bl[2*nn+1][0], bl[2*nn+1][1],
                  sb + SM_W1L + off);
        }
        #pragma unroll
        for (int m = 0; m < 2; m++)
            #pragma unroll
            for (int n = 0; n < 8; n++) {
                MMA16816(acc[m][n], ah[m], bh[n]);
                MMA16816(acc[m][n], ah[m], bl[n]);
                MMA16816(acc[m][n], al[m], bh[n]);
            }
    }
    __syncthreads();   // all GEMM1 smem reads done before A overwrite

    // --- epilogue1: +b1, relu -> emb global; bf16 hi/lo back into sAh/sAl ---
    {
        const int qr = lane >> 2;                 // 0..7
        const int qc = (lane & 3) * 2;            // 0,2,4,6
        #pragma unroll
        for (int m = 0; m < 2; m++) {
            #pragma unroll
            for (int n = 0; n < 8; n++) {
                int col = wn * 64 + n * 8 + qc;
                float bA = sBias[col], bB = sBias[col + 1];
                #pragma unroll
                for (int h = 0; h < 2; h++) {     // row halves r, r+8
                    int row = wm * 32 + m * 16 + qr + h * 8;
                    float v0 = fmaxf(acc[m][n][h * 2 + 0] + bA, 0.f);
                    float v1 = fmaxf(acc[m][n][h * 2 + 1] + bB, 0.f);
                    int node = node0 + row;
                    if (node < N_NODES)
                        *(float2*)(emb + (size_t)node * F + col) = make_float2(v0, v1);
                    __nv_bfloat16 h0 = __float2bfloat16(v0);
                    __nv_bfloat16 h1 = __float2bfloat16(v1);
                    __nv_bfloat16 l0 = __float2bfloat16(v0 - __bfloat162float(h0));
                    __nv_bfloat16 l1 = __float2bfloat16(v1 - __bfloat162float(h1));
                    __nv_bfloat162 ph = __halves2bfloat162(h0, h1);
                    __nv_bfloat162 pl = __halves2bfloat162(l0, l1);
                    *(uint32_t*)(smem + SM_AH + row * RSB + col * 2) = *(uint32_t*)&ph;
                    *(uint32_t*)(smem + SM_AL + row * RSB + col * 2) = *(uint32_t*)&pl;
                }
            }
        }
    }
    __syncthreads();

    // ================= GEMM2: [128 x 64] ==================
    const int wn2 = wid >> 2;                     // cols [wn2*32, +32)
    float acc2[2][4][4];
    #pragma unroll
    for (int m = 0; m < 2; m++)
        #pragma unroll
        for (int n = 0; n < 4; n++)
            #pragma unroll
            for (int q = 0; q < 4; q++) acc2[m][n][q] = 0.f;

    #pragma unroll
    for (int ks = 0; ks < 8; ks++) {
        const int k0 = ks * 16;
        uint32_t ah[2][4], al[2][4];
        #pragma unroll
        for (int m = 0; m < 2; m++) {
            int row = wm * 32 + m * 16 + a_row;
            uint32_t off = row * RSB + (k0 + a_kof) * 2;
            LDSM4(ah[m][0], ah[m][1], ah[m][2], ah[m][3], sb + SM_AH + off);
            LDSM4(al[m][0], al[m][1], al[m][2], al[m][3], sb + SM_AL + off);
        }
        uint32_t bh[4][2], bl[4][2];
        #pragma unroll
        for (int nn = 0; nn < 2; nn++) {
            int row = wn2 * 32 + nn * 16 + b_row;
            uint32_t off = row * RSB + (k0 + b_kof) * 2;
            LDSM4(bh[2*nn][0], bh[2*nn][1], bh[2*nn+1][0], bh[2*nn+1][1],
                  sb + SM_W2H + off);
            LDSM4(bl[2*nn][0], bl[2*nn][1], bl[2*nn+1][0], bl[2*nn+1][1],
                  sb + SM_W2L + off);
        }
        #pragma unroll
        for (int m = 0; m < 2; m++)
            #pragma unroll
            for (int n = 0; n < 4; n++) {
                MMA16816(acc2[m][n], ah[m], bh[n]);
                MMA16816(acc2[m][n], ah[m], bl[n]);
                MMA16816(acc2[m][n], al[m], bh[n]);
            }
    }

    // --- epilogue2: +b2 -> out ---
    {
        const int qr = lane >> 2;
        const int qc = (lane & 3) * 2;
        #pragma unroll
        for (int m = 0; m < 2; m++) {
            #pragma unroll
            for (int n = 0; n < 4; n++) {
                int col = wn2 * 32 + n * 8 + qc;
                float bA = sBias[F + col], bB = sBias[F + col + 1];
                #pragma unroll
                for (int h = 0; h < 2; h++) {
                    int row = wm * 32 + m * 16 + qr + h * 8;
                    int node = node0 + row;
                    if (node < N_NODES) {
                        float v0 = acc2[m][n][h * 2 + 0] + bA;
                        float v1 = acc2[m][n][h * 2 + 1] + bB;
                        *(float2*)(out + (size_t)node * C + col) = make_float2(v0, v1);
                    }
                }
            }
        }
    }
}

// ---------------------------------------------------------------------------
extern "C" void kernel_launch(void* const* d_in, const int* in_sizes, int n_in,
                              void* d_out, int out_size) {
    const float* x   = (const float*)d_in[0];
    const int*   src = (const int*)d_in[1];
    const int*   dst = (const int*)d_in[2];
    const float* W1  = (const float*)d_in[3];
    const float* b1  = (const float*)d_in[4];
    const float* W2  = (const float*)d_in[5];
    const float* b2  = (const float*)d_in[6];

    float* out = (float*)d_out;                       // [N_NODES, 64]
    float* emb = out + (size_t)N_NODES * C;           // [N_NODES, 128]

    // CSR build
    k_zero<<<(N_NODES + 255) / 256, 256>>>();
    k_hist<<<(N_EDGES + 255) / 256, 256>>>(dst);
    k_scan_block<<<N_SCANBLK, SCAN_B>>>();
    k_scan_top<<<1, 256>>>();
    k_rowptr<<<(N_NODES + 255) / 256, 256>>>();
    k_fill<<<(N_EDGES + 255) / 256, 256>>>(src, dst);

    // weight split/transpose
    k_wprep<<<(F * F + 255) / 256, 256>>>(W1, W2);

    // gather-sum + normalize + bf16 split
    k_gather<<<(N_NODES * 32 + 255) / 256, 256>>>(x);

    // mma.sync fused GEMMs
    cudaFuncSetAttribute(k_gemm_mma, cudaFuncAttributeMaxDynamicSharedMemorySize,
                         SMEM_MM);
    int gblocks = (N_NODES + 127) / 128;              // 782
    k_gemm_mma<<<gblocks, 256, SMEM_MM>>>(b1, b2, out, emb);
}